// round 8
// baseline (speedup 1.0000x reference)
#include <cuda_runtime.h>
#include <math.h>

// Problem constants: N_OBJ=1024, C_DET=8, C_SEG=4, H=W=28
#define C_DET 8
#define C_SEG 4
#define HW4 196          // 28*28/4 (float4 units)
#define N_OBJ 1024
#define NB 8             // objects per block (one per warp)
#define NCHUNK (N_OBJ / NB)   // 128
#define RTHREADS 256
#define NITER ((HW4 + 31) / 32)   // 7
#define MAX_EDGES 64
#define NBLOCKS (NCHUNK * C_DET)  // 1024

// Per-block partial sums, k-major. Fully overwritten each launch.
__device__ float g_part[5][C_DET][NCHUNK];
__device__ unsigned int g_count;   // ticket; reset by the last block
__device__ float g_sink;           // DCE-blocker for L2 warm-up

// Fused: streaming reduction + (last block) full tail.
// __launch_bounds__(256,7): single wave (1036 slots >= 1024 blocks).
__global__ __launch_bounds__(RTHREADS, 7) void fused_kernel(
    const float4* __restrict__ det4,   // (N,C_DET,HW4) float4
    const float4* __restrict__ seg4,   // (N,C_DET,C_SEG,HW4) float4
    const float*  __restrict__ dcp,    // (N_OBJ, C_DET)
    const int*    __restrict__ edge_i, // int32
    const int*    __restrict__ edge_j,
    int n_edges,
    float* __restrict__ out)
{
    const int c   = blockIdx.y;
    const int tid = threadIdx.x;
    const int wid = tid >> 5;
    const int lid = tid & 31;
    const int n   = blockIdx.x * NB + wid;

    // ---------- Phase A: streaming reduction (the 128.5 MB scan) ----------
    const size_t mb = (size_t)n * C_DET + c;
    const float4* __restrict__ dp = det4 + mb * HW4;
    const float4* __restrict__ sp = seg4 + mb * (C_SEG * HW4);

    float dsum = 0.0f;
    float a0 = 0.0f, a1 = 0.0f, a2 = 0.0f, a3 = 0.0f;

    #pragma unroll
    for (int it = 0; it < NITER; it++) {
        const int q = lid + it * 32;
        if (q < HW4) {
            const float4 d  = __ldcs(dp + q);
            const float4 s0 = __ldcs(sp + 0 * HW4 + q);
            const float4 s1 = __ldcs(sp + 1 * HW4 + q);
            const float4 s2 = __ldcs(sp + 2 * HW4 + q);
            const float4 s3 = __ldcs(sp + 3 * HW4 + q);
            dsum += (d.x + d.y) + (d.z + d.w);
            a0 += d.x * s0.x + d.y * s0.y + d.z * s0.z + d.w * s0.w;
            a1 += d.x * s1.x + d.y * s1.y + d.z * s1.z + d.w * s1.w;
            a2 += d.x * s2.x + d.y * s2.y + d.z * s2.z + d.w * s2.w;
            a3 += d.x * s3.x + d.y * s3.y + d.z * s3.z + d.w * s3.w;
        }
    }

    #pragma unroll
    for (int off = 16; off; off >>= 1) {
        dsum += __shfl_xor_sync(0xFFFFFFFFu, dsum, off);
        a0   += __shfl_xor_sync(0xFFFFFFFFu, a0, off);
        a1   += __shfl_xor_sync(0xFFFFFFFFu, a1, off);
        a2   += __shfl_xor_sync(0xFFFFFFFFu, a2, off);
        a3   += __shfl_xor_sync(0xFFFFFFFFu, a3, off);
    }

    __shared__ float sm[5][RTHREADS / 32];
    if (lid == 0) {
        sm[0][wid] = dsum; sm[1][wid] = a0; sm[2][wid] = a1;
        sm[3][wid] = a2;   sm[4][wid] = a3;
    }
    __syncthreads();

    if (tid < 5) {
        float r = 0.0f;
        #pragma unroll
        for (int w = 0; w < RTHREADS / 32; w++) r += sm[tid][w];
        g_part[tid][c][blockIdx.x] = r;
    }

    // L2 warm-up of dcp + edges (one early-finishing block) so the tail hits L2.
    if (blockIdx.x == 0 && c == 0) {
        const float4* dcp4 = (const float4*)dcp;
        float acc = 0.0f;
        for (int i = tid; i < N_OBJ * C_DET / 4; i += RTHREADS) {
            const float4 v = __ldcg(dcp4 + i);
            acc += v.x + v.y + v.z + v.w;
        }
        if (tid < n_edges)
            acc += (float)(__ldcg(edge_i + tid) + __ldcg(edge_j + tid));
        if (tid == 0) g_sink = acc;  // deterministic overwrite
    }

    // ---------- Ticket: last block runs the tail ----------
    __threadfence();
    __shared__ unsigned int s_last;
    if (tid == 0)
        s_last = (atomicAdd(&g_count, 1u) == NBLOCKS - 1) ? 1u : 0u;
    __syncthreads();
    if (!s_last) return;
    if (tid == 0) g_count = 0;  // reset for next graph replay

    // ---------- Tail (256 threads, all data L2-resident) ----------
    __shared__ double s_acc[C_DET][5];
    __shared__ float  s_w[C_DET];
    __shared__ float  s_red[RTHREADS / 32];
    __shared__ int    s_ei[MAX_EDGES], s_ej[MAX_EDGES];

    // Parallel edge load (one thread per edge, single L2-hit round).
    if (tid < n_edges) { s_ei[tid] = edge_i[tid]; s_ej[tid] = edge_j[tid]; }

    // Phase B: warp w sums class w; fixed-order double combine (deterministic).
    {
        const int cc = wid;  // 8 warps, 8 classes
        #pragma unroll
        for (int k = 0; k < 5; k++) {
            const float* p = g_part[k][cc];
            double s = ((double)p[lid] + (double)p[lid + 32])
                     + ((double)p[lid + 64] + (double)p[lid + 96]);
            #pragma unroll
            for (int off = 16; off; off >>= 1)
                s += __shfl_xor_sync(0xFFFFFFFFu, s, off);
            if (lid == 0) s_acc[cc][k] = s;
        }
    }
    __syncthreads();

    // Phase C: edge weights from shared indices (atomic-free, deterministic).
    if (tid < C_DET) {
        double acc = 0.0;
        for (int e = 0; e < n_edges; e++)
            if (s_ej[e] == tid)
                acc += s_acc[tid][1 + s_ei[e]] / s_acc[tid][0];
        s_w[tid] = (float)acc;
    }
    __syncthreads();

    // Phase D: per-object prob + BCE mean (4 objects per thread, L2-warm dcp).
    float w[C_DET];
    #pragma unroll
    for (int k = 0; k < C_DET; k++) w[k] = s_w[k];

    const float4* dcp4 = (const float4*)dcp;
    float l = 0.0f;
    #pragma unroll
    for (int o = 0; o < N_OBJ / RTHREADS; o++) {
        const int obj = o * RTHREADS + tid;
        const float4 d0 = dcp4[obj * 2 + 0];
        const float4 d1 = dcp4[obj * 2 + 1];
        float p = d0.x * w[0] + d0.y * w[1] + d0.z * w[2] + d0.w * w[3]
                + d1.x * w[4] + d1.y * w[5] + d1.z * w[6] + d1.w * w[7];
        l += -fmaxf(logf(p), -100.0f);
    }

    #pragma unroll
    for (int off = 16; off; off >>= 1) l += __shfl_xor_sync(0xFFFFFFFFu, l, off);
    if (lid == 0) s_red[wid] = l;
    __syncthreads();

    if (tid == 0) {
        float v = 0.0f;
        #pragma unroll
        for (int i = 0; i < RTHREADS / 32; i++) v += s_red[i];
        out[0] = v / (float)N_OBJ;
    }
}

extern "C" void kernel_launch(void* const* d_in, const int* in_sizes, int n_in,
                              void* d_out, int out_size) {
    // metadata order: det_class_probs (f32), det_mask_probs (f32),
    //                 seg_mask_probs (f32), edge_i (i32), edge_j (i32)
    const float*  dcp = (const float*)d_in[0];
    const float4* det = (const float4*)d_in[1];
    const float4* seg = (const float4*)d_in[2];
    const int*    ei  = (const int*)d_in[3];
    const int*    ej  = (const int*)d_in[4];
    const int n_edges = in_sizes[3] < MAX_EDGES ? in_sizes[3] : MAX_EDGES;
    float* out = (float*)d_out;

    fused_kernel<<<dim3(NCHUNK, C_DET), RTHREADS>>>(det, seg, dcp, ei, ej, n_edges, out);
}